// round 1
// baseline (speedup 1.0000x reference)
#include <cuda_runtime.h>
#include <math.h>

#define Nn    16384
#define Bg    16
#define NPG   1024
#define Kk    12
#define DM    128
#define DH    256
#define Ll    3

// ---------------- device scratch (no allocs allowed) ----------------
__device__ float g_h  [Nn * DM];
__device__ float g_ta [Nn * DH];   // also reused for in_hidden (N x 128) and gate hidden (N x 128)
__device__ float g_tb [Nn * DH];
__device__ float g_s  [Nn * DH];
__device__ float g_agg[Nn * DM];
__device__ float g_uh [Nn * DH];
__device__ float g_ea [Nn * Kk * 4];
__device__ int   g_knn[Nn * Kk];
__device__ float g_gl [Nn];
__device__ float g_part[Bg * 8 * DM];
__device__ float g_mean[Bg * DM];
__device__ float g_var [Bg * DM];

__device__ __forceinline__ float siluf(float v) { return v / (1.f + expf(-v)); }

// ---------------- KNN + edge attrs ----------------
__global__ __launch_bounds__(256) void knn_kernel(const float* __restrict__ x,
                                                  int* __restrict__ knn,
                                                  float* __restrict__ ea) {
    __shared__ float px[NPG], py[NPG], d2[NPG];
    __shared__ float rd[256];
    __shared__ int   ri[256];
    const float INF = __int_as_float(0x7f800000);
    int n = blockIdx.x;
    int g = n >> 10;
    int li = n & 1023;
    int base = g << 10;
    int tid = threadIdx.x;
    for (int t = tid; t < NPG; t += 256) {
        px[t] = x[(base + t) * 3 + 1];
        py[t] = x[(base + t) * 3 + 2];
    }
    __syncthreads();
    float mx = px[li], my = py[li];
    for (int t = tid; t < NPG; t += 256) {
        float dx = __fsub_rn(px[t], mx);
        float dy = __fsub_rn(py[t], my);
        float v = __fadd_rn(__fmul_rn(dx, dx), __fmul_rn(dy, dy));
        d2[t] = (t == li) ? INF : v;
    }
    __syncthreads();
    for (int p = 0; p < Kk; ++p) {
        float bd = INF;
        int bi = 1 << 20;
        for (int t = tid; t < NPG; t += 256) {
            float v = d2[t];
            if (v < bd || (v == bd && t < bi)) { bd = v; bi = t; }
        }
        rd[tid] = bd; ri[tid] = bi;
        __syncthreads();
        for (int s = 128; s > 0; s >>= 1) {
            if (tid < s) {
                float vo = rd[tid + s]; int io = ri[tid + s];
                if (vo < rd[tid] || (vo == rd[tid] && io < ri[tid])) { rd[tid] = vo; ri[tid] = io; }
            }
            __syncthreads();
        }
        int w = ri[0];
        if (tid == 0) {
            knn[n * Kk + p] = base + w;
            float dpx = px[w] - mx, dpy = py[w] - my;
            float dist = sqrtf(dpx * dpx + dpy * dpy + 1e-12f);
            float ds = x[(base + w) * 3] - x[n * 3];
            float* e = ea + (n * Kk + p) * 4;
            e[0] = dpx; e[1] = dpy; e[2] = dist; e[3] = ds;
            d2[w] = INF;
        }
        __syncthreads();
    }
}

// ---------------- input MLP hidden ----------------
__global__ void in_hidden_kernel(const float* __restrict__ x,
                                 const float* __restrict__ W1,
                                 const float* __restrict__ b1,
                                 float* __restrict__ out) {
    int n = blockIdx.x;
    int j = threadIdx.x;
    float x0 = x[n * 3], x1 = x[n * 3 + 1], x2 = x[n * 3 + 2];
    float t = b1[j] + x0 * W1[j] + x1 * W1[DM + j] + x2 * W1[2 * DM + j];
    out[n * DM + j] = siluf(t);
}

// ---------------- generic fused GEMM ----------------
// C[M x N] = act( A0@B0 + (A1@B1) + bias*biasScale + R )
// A row-major (ld = K), B row-major (ld = N). M % 128 == 0, N % 128 == 0, K % 16 == 0.
__global__ __launch_bounds__(256) void gemm_kernel(
    const float* __restrict__ A0, const float* __restrict__ B0, int K0,
    const float* __restrict__ A1, const float* __restrict__ B1, int K1,
    const float* __restrict__ bias, float biasScale,
    const float* __restrict__ R,
    float* __restrict__ C, int N, int act) {
    __shared__ float As[16][132];
    __shared__ float Bs[16][128];
    int tid = threadIdx.x;
    int tx = tid & 15, ty = tid >> 4;
    int rowBase = blockIdx.y * 128;
    int colBase = blockIdx.x * 128;
    float c[8][8] = {};
    float a[8], b[8];
    for (int part = 0; part < 2; ++part) {
        const float* A = part ? A1 : A0;
        const float* B = part ? B1 : B0;
        int K = part ? K1 : K0;
        if (A == nullptr) continue;
        for (int k0 = 0; k0 < K; k0 += 16) {
#pragma unroll
            for (int r = 0; r < 8; ++r) {
                int idx = tid + r * 256;
                int m = idx >> 4, kk = idx & 15;
                As[kk][m] = A[(rowBase + m) * K + k0 + kk];
            }
#pragma unroll
            for (int r = 0; r < 8; ++r) {
                int idx = tid + r * 256;
                int nn = idx & 127, kk = idx >> 7;
                Bs[kk][nn] = B[(k0 + kk) * N + colBase + nn];
            }
            __syncthreads();
#pragma unroll
            for (int kk = 0; kk < 16; ++kk) {
#pragma unroll
                for (int i = 0; i < 8; ++i) a[i] = As[kk][ty * 8 + i];
#pragma unroll
                for (int j = 0; j < 8; ++j) b[j] = Bs[kk][tx * 8 + j];
#pragma unroll
                for (int i = 0; i < 8; ++i)
#pragma unroll
                    for (int j = 0; j < 8; ++j)
                        c[i][j] += a[i] * b[j];
            }
            __syncthreads();
        }
    }
#pragma unroll
    for (int i = 0; i < 8; ++i) {
        int row = rowBase + ty * 8 + i;
#pragma unroll
        for (int j = 0; j < 8; ++j) {
            int col = colBase + tx * 8 + j;
            float v = c[i][j];
            if (bias) v += bias[col] * biasScale;
            if (R) v += R[row * N + col];
            if (act == 1) v = siluf(v);
            else if (act == 2) v = tanhf(v);
            C[row * N + col] = v;
        }
    }
}

// ---------------- per-edge hidden + silu + aggregate ----------------
__global__ __launch_bounds__(256) void edge_kernel(const float* __restrict__ ta,
                                                   const float* __restrict__ tb,
                                                   const int* __restrict__ knn,
                                                   const float* __restrict__ ea,
                                                   const float* __restrict__ W1c,
                                                   float* __restrict__ s) {
    __shared__ int   ksh[Kk];
    __shared__ float esh[Kk * 4];
    int n = blockIdx.x;
    int c = threadIdx.x;
    if (c < Kk) ksh[c] = knn[n * Kk + c];
    if (c < Kk * 4) esh[c] = ea[n * Kk * 4 + c];
    __syncthreads();
    float w0 = W1c[c], w1 = W1c[DH + c], w2 = W1c[2 * DH + c], w3 = W1c[3 * DH + c];
    float tav = ta[n * DH + c];
    float acc = 0.f;
#pragma unroll
    for (int j = 0; j < Kk; ++j) {
        int src = ksh[j];
        float v = tav + tb[src * DH + c]
                + esh[4 * j] * w0 + esh[4 * j + 1] * w1
                + esh[4 * j + 2] * w2 + esh[4 * j + 3] * w3;
        acc += siluf(v);
    }
    s[n * DH + c] = acc;
}

// ---------------- graph norm (deterministic two-stage) ----------------
__global__ void norm_sum(const float* __restrict__ h, float* __restrict__ part) {
    int b = blockIdx.x >> 3, sl = blockIdx.x & 7, c = threadIdx.x;
    int row0 = (b << 10) + (sl << 7);
    float acc = 0.f;
    for (int r = 0; r < 128; ++r) acc += h[(row0 + r) * DM + c];
    part[blockIdx.x * DM + c] = acc;
}
__global__ void norm_fin(const float* __restrict__ part, float* __restrict__ out) {
    int b = blockIdx.x, c = threadIdx.x;
    float acc = 0.f;
    for (int s = 0; s < 8; ++s) acc += part[(b * 8 + s) * DM + c];
    out[b * DM + c] = acc * (1.f / 1024.f);
}
__global__ void norm_apply(float* __restrict__ h, const float* __restrict__ mean,
                           const float* __restrict__ ms, float* __restrict__ part) {
    int b = blockIdx.x >> 3, sl = blockIdx.x & 7, c = threadIdx.x;
    int row0 = (b << 10) + (sl << 7);
    float mv = mean[b * DM + c] * ms[c];
    float acc = 0.f;
    for (int r = 0; r < 128; ++r) {
        float o = h[(row0 + r) * DM + c] - mv;
        h[(row0 + r) * DM + c] = o;
        acc += o * o;
    }
    part[blockIdx.x * DM + c] = acc;
}
__global__ void norm_scale(float* __restrict__ h, const float* __restrict__ var,
                           const float* __restrict__ w, const float* __restrict__ bb) {
    int b = blockIdx.x >> 3, sl = blockIdx.x & 7, c = threadIdx.x;
    int row0 = (b << 10) + (sl << 7);
    float inv = 1.f / sqrtf(var[b * DM + c] + 1e-5f);
    float wc = w[c] * inv, bc = bb[c];
    for (int r = 0; r < 128; ++r)
        h[(row0 + r) * DM + c] = h[(row0 + r) * DM + c] * wc + bc;
}

// ---------------- gate logit GEMV ----------------
__global__ void gl_kernel(const float* __restrict__ ghid, const float* __restrict__ W2,
                          const float* __restrict__ b2, float* __restrict__ gl) {
    int node = blockIdx.x * 8 + (threadIdx.x >> 5);
    int lane = threadIdx.x & 31;
    float acc = 0.f;
#pragma unroll
    for (int r = 0; r < 4; ++r) acc += ghid[node * DM + lane + 32 * r] * W2[lane + 32 * r];
#pragma unroll
    for (int o = 16; o; o >>= 1) acc += __shfl_down_sync(0xffffffffu, acc, o);
    if (lane == 0) gl[node] = acc + b2[0];
}

// ---------------- softmax pool + head ----------------
__global__ __launch_bounds__(1024) void pool_head(const float* __restrict__ h,
                                                  const float* __restrict__ gl,
                                                  const float* __restrict__ hW1,
                                                  const float* __restrict__ hb1,
                                                  const float* __restrict__ hW2,
                                                  const float* __restrict__ hb2,
                                                  float* __restrict__ out) {
    __shared__ float red[1024];
    __shared__ float ash[1024];
    __shared__ float pool[1024];
    __shared__ float pvec[128];
    __shared__ float hid[128];
    int g = blockIdx.x, tid = threadIdx.x;
    float gv = gl[g * NPG + tid];
    red[tid] = gv;
    __syncthreads();
    for (int s = 512; s > 0; s >>= 1) {
        if (tid < s) red[tid] = fmaxf(red[tid], red[tid + s]);
        __syncthreads();
    }
    float gmax = red[0];
    __syncthreads();
    float e = expf(gv - gmax);
    red[tid] = e;
    __syncthreads();
    for (int s = 512; s > 0; s >>= 1) {
        if (tid < s) red[tid] += red[tid + s];
        __syncthreads();
    }
    float ssum = red[0];
    __syncthreads();
    ash[tid] = e / ssum;
    __syncthreads();
    int r = tid >> 7, c = tid & 127;
    float acc = 0.f;
    for (int n = r; n < NPG; n += 8)
        acc += ash[n] * h[(g * NPG + n) * DM + c];
    pool[tid] = acc;
    __syncthreads();
    if (tid < 128) {
        float p = 0.f;
        for (int q = 0; q < 8; ++q) p += pool[q * 128 + tid];
        pvec[tid] = p;
    }
    __syncthreads();
    if (tid < 128) {
        float t = hb1[tid];
        for (int k = 0; k < 128; ++k) t += pvec[k] * hW1[k * DM + tid];
        hid[tid] = siluf(t);
    }
    __syncthreads();
    if (tid < 128) red[tid] = hid[tid] * hW2[tid];
    __syncthreads();
    for (int s = 64; s > 0; s >>= 1) {
        if (tid < s) red[tid] += red[tid + s];
        __syncthreads();
    }
    if (tid == 0) out[g] = red[0] + hb2[0];
}

// ---------------- host orchestration ----------------
extern "C" void kernel_launch(void* const* d_in, const int* in_sizes, int n_in,
                              void* d_out, int out_size) {
    (void)in_sizes; (void)n_in; (void)out_size;
    const float* x      = (const float*)d_in[0];
    const float* in_W1  = (const float*)d_in[2];
    const float* in_b1  = (const float*)d_in[3];
    const float* in_W2  = (const float*)d_in[4];
    const float* in_b2  = (const float*)d_in[5];
    const float* msg_W1 = (const float*)d_in[6];
    const float* msg_b1 = (const float*)d_in[7];
    const float* msg_W2 = (const float*)d_in[8];
    const float* msg_b2 = (const float*)d_in[9];
    const float* upd_W1 = (const float*)d_in[10];
    const float* upd_b1 = (const float*)d_in[11];
    const float* upd_W2 = (const float*)d_in[12];
    const float* upd_b2 = (const float*)d_in[13];
    const float* norm_w = (const float*)d_in[14];
    const float* norm_b = (const float*)d_in[15];
    const float* norm_ms= (const float*)d_in[16];
    const float* gate_W1= (const float*)d_in[17];
    const float* gate_b1= (const float*)d_in[18];
    const float* gate_W2= (const float*)d_in[19];
    const float* gate_b2= (const float*)d_in[20];
    const float* head_W1= (const float*)d_in[21];
    const float* head_b1= (const float*)d_in[22];
    const float* head_W2= (const float*)d_in[23];
    const float* head_b2= (const float*)d_in[24];
    float* out = (float*)d_out;

    float *hb, *tab, *tbb, *sb, *aggb, *uhb, *eab, *glb, *partb, *meanb, *varb;
    int* knnb;
    cudaGetSymbolAddress((void**)&hb,   g_h);
    cudaGetSymbolAddress((void**)&tab,  g_ta);
    cudaGetSymbolAddress((void**)&tbb,  g_tb);
    cudaGetSymbolAddress((void**)&sb,   g_s);
    cudaGetSymbolAddress((void**)&aggb, g_agg);
    cudaGetSymbolAddress((void**)&uhb,  g_uh);
    cudaGetSymbolAddress((void**)&eab,  g_ea);
    cudaGetSymbolAddress((void**)&knnb, g_knn);
    cudaGetSymbolAddress((void**)&glb,  g_gl);
    cudaGetSymbolAddress((void**)&partb,g_part);
    cudaGetSymbolAddress((void**)&meanb,g_mean);
    cudaGetSymbolAddress((void**)&varb, g_var);

    // 1. KNN + edge attrs
    knn_kernel<<<Nn, 256>>>(x, knnb, eab);

    // 2. input MLP: hidden -> g_ta (N x 128), then h = hidden @ in_W2 + b2
    in_hidden_kernel<<<Nn, DM>>>(x, in_W1, in_b1, tab);
    {
        dim3 grid(DM / 128, Nn / 128);
        gemm_kernel<<<grid, 256>>>(tab, in_W2, DM, nullptr, nullptr, 0,
                                   in_b2, 1.f, nullptr, hb, DM, 0);
    }

    for (int i = 0; i < Ll; ++i) {
        const float* W1i = msg_W1 + (size_t)i * 260 * DH;
        const float* b1i = msg_b1 + (size_t)i * DH;
        const float* W2i = msg_W2 + (size_t)i * DH * DM;
        const float* b2i = msg_b2 + (size_t)i * DM;
        const float* U1i = upd_W1 + (size_t)i * 2 * DM * DH;
        const float* ub1i= upd_b1 + (size_t)i * DH;
        const float* U2i = upd_W2 + (size_t)i * DH * DM;
        const float* ub2i= upd_b2 + (size_t)i * DM;
        const float* nwi = norm_w + (size_t)i * DM;
        const float* nbi = norm_b + (size_t)i * DM;
        const float* nmi = norm_ms+ (size_t)i * DM;

        dim3 grid256(DH / 128, Nn / 128);
        dim3 grid128(DM / 128, Nn / 128);
        // ta = h @ W1[0:128] + b1 ; tb = h @ W1[128:256]
        gemm_kernel<<<grid256, 256>>>(hb, W1i, DM, nullptr, nullptr, 0,
                                      b1i, 1.f, nullptr, tab, DH, 0);
        gemm_kernel<<<grid256, 256>>>(hb, W1i + DM * DH, DM, nullptr, nullptr, 0,
                                      nullptr, 0.f, nullptr, tbb, DH, 0);
        // s[n] = sum_j silu(ta[n] + tb[src] + ea @ W1[256:260])
        edge_kernel<<<Nn, DH>>>(tab, tbb, knnb, eab, W1i + 2 * DM * DH, sb);
        // agg = s @ W2 + 12*b2
        gemm_kernel<<<grid128, 256>>>(sb, W2i, DH, nullptr, nullptr, 0,
                                      b2i, 12.f, nullptr, aggb, DM, 0);
        // uh = silu(h @ U1[0:128] + agg @ U1[128:256] + ub1)
        gemm_kernel<<<grid256, 256>>>(hb, U1i, DM, aggb, U1i + DM * DH, DM,
                                      ub1i, 1.f, nullptr, uhb, DH, 1);
        // h = h + uh @ U2 + ub2
        gemm_kernel<<<grid128, 256>>>(uhb, U2i, DH, nullptr, nullptr, 0,
                                      ub2i, 1.f, hb, hb, DM, 0);
        // graph norm
        norm_sum<<<Bg * 8, DM>>>(hb, partb);
        norm_fin<<<Bg, DM>>>(partb, meanb);
        norm_apply<<<Bg * 8, DM>>>(hb, meanb, nmi, partb);
        norm_fin<<<Bg, DM>>>(partb, varb);
        norm_scale<<<Bg * 8, DM>>>(hb, varb, nwi, nbi);
    }

    // gate: ghid = tanh(h @ gate_W1 + gate_b1)  (reuse g_ta)
    {
        dim3 grid(DM / 128, Nn / 128);
        gemm_kernel<<<grid, 256>>>(hb, gate_W1, DM, nullptr, nullptr, 0,
                                   gate_b1, 1.f, nullptr, tab, DM, 2);
    }
    gl_kernel<<<Nn / 8, 256>>>(tab, gate_W2, gate_b2, glb);
    pool_head<<<Bg, 1024>>>(hb, glb, head_W1, head_b1, head_W2, head_b2, out);
}

// round 2
// speedup vs baseline: 1.7223x; 1.7223x over previous
#include <cuda_runtime.h>
#include <math.h>

#define Nn    16384
#define Bg    16
#define NPG   1024
#define Kk    12
#define DM    128
#define DH    256
#define Ll    3

// ---------------- device scratch (no allocs allowed) ----------------
__device__ float g_h  [Nn * DM];
__device__ float g_ta [Nn * DH];
__device__ float g_tb [Nn * DH];
__device__ float g_s  [Nn * DH];
__device__ float g_agg[Nn * DM];
__device__ float g_uh [Nn * DH];
__device__ float g_ea [Nn * Kk * 4];
__device__ int   g_knn[Nn * Kk];
__device__ float g_gl [Nn];
__device__ float g_part[Bg * 8 * DM];
__device__ float g_mean[Bg * DM];
__device__ float g_var [Bg * DM];

__device__ __forceinline__ float siluf(float v) { return v / (1.f + expf(-v)); }

__device__ __forceinline__ unsigned f2tf32(float f) {
    unsigned u;
    asm("cvt.rna.tf32.f32 %0, %1;" : "=r"(u) : "f"(f));
    return u;
}

__device__ __forceinline__ void mma_tf32(float& c0, float& c1, float& c2, float& c3,
                                         unsigned a0, unsigned a1, unsigned a2, unsigned a3,
                                         unsigned b0, unsigned b1) {
    asm volatile("mma.sync.aligned.m16n8k8.row.col.f32.tf32.tf32.f32 "
                 "{%0,%1,%2,%3},{%4,%5,%6,%7},{%8,%9},{%0,%1,%2,%3};"
                 : "+f"(c0), "+f"(c1), "+f"(c2), "+f"(c3)
                 : "r"(a0), "r"(a1), "r"(a2), "r"(a3), "r"(b0), "r"(b1));
}

// ---------------- KNN + edge attrs (warp-shuffle selection) ----------------
__global__ __launch_bounds__(256) void knn_kernel(const float* __restrict__ x,
                                                  int* __restrict__ knn,
                                                  float* __restrict__ ea) {
    __shared__ float px[NPG], py[NPG], d2[NPG];
    __shared__ unsigned long long wred[8];
    const float INF = __int_as_float(0x7f800000);
    int n = blockIdx.x;
    int g = n >> 10;
    int li = n & 1023;
    int base = g << 10;
    int tid = threadIdx.x;
    int lane = tid & 31, warp = tid >> 5;
    for (int t = tid; t < NPG; t += 256) {
        px[t] = x[(base + t) * 3 + 1];
        py[t] = x[(base + t) * 3 + 2];
    }
    __syncthreads();
    float mx = px[li], my = py[li];
    for (int t = tid; t < NPG; t += 256) {
        float dx = __fsub_rn(px[t], mx);
        float dy = __fsub_rn(py[t], my);
        float v = __fadd_rn(__fmul_rn(dx, dx), __fmul_rn(dy, dy));
        d2[t] = (t == li) ? INF : v;
    }
    __syncthreads();
    for (int p = 0; p < Kk; ++p) {
        float bd = INF;
        int bi = 1 << 20;
#pragma unroll
        for (int r = 0; r < 4; ++r) {
            int t = tid + r * 256;
            float v = d2[t];
            if (v < bd || (v == bd && t < bi)) { bd = v; bi = t; }
        }
        // pack (d2 bits, index): d2 >= 0 so float bits are order-preserving
        unsigned long long key = ((unsigned long long)__float_as_uint(bd) << 32) | (unsigned)bi;
#pragma unroll
        for (int o = 16; o; o >>= 1) {
            unsigned long long other = __shfl_xor_sync(0xffffffffu, key, o);
            if (other < key) key = other;
        }
        if (lane == 0) wred[warp] = key;
        __syncthreads();
        if (tid == 0) {
            unsigned long long best = wred[0];
#pragma unroll
            for (int q = 1; q < 8; ++q) if (wred[q] < best) best = wred[q];
            int w = (int)(best & 0xffffffffu);
            knn[n * Kk + p] = base + w;
            float dpx = px[w] - mx, dpy = py[w] - my;
            float dist = sqrtf(dpx * dpx + dpy * dpy + 1e-12f);
            float ds = x[(base + w) * 3] - x[n * 3];
            float* e = ea + (n * Kk + p) * 4;
            e[0] = dpx; e[1] = dpy; e[2] = dist; e[3] = ds;
            d2[w] = INF;
        }
        __syncthreads();
    }
}

// ---------------- input MLP hidden ----------------
__global__ void in_hidden_kernel(const float* __restrict__ x,
                                 const float* __restrict__ W1,
                                 const float* __restrict__ b1,
                                 float* __restrict__ out) {
    int n = blockIdx.x;
    int j = threadIdx.x;
    float x0 = x[n * 3], x1 = x[n * 3 + 1], x2 = x[n * 3 + 2];
    float t = b1[j] + x0 * W1[j] + x1 * W1[DM + j] + x2 * W1[2 * DM + j];
    out[n * DM + j] = siluf(t);
}

// ---------------- tf32 tensor-core fused GEMM ----------------
// C[M x N] = act( A0@B0 + (A1@B1) + bias*biasScale + R )
// A row-major (ld = K), B row-major (ld = N). M%128==0, N%128==0, K%16==0.
__global__ __launch_bounds__(256) void gemm_tf32(
    const float* __restrict__ A0, const float* __restrict__ B0, int K0,
    const float* __restrict__ A1, const float* __restrict__ B1, int K1,
    const float* __restrict__ bias, float biasScale,
    const float* __restrict__ R,
    float* __restrict__ Cout, int N, int act) {
    __shared__ __align__(16) unsigned As[128][20];   // [m][k] pad 20 -> conflict-free
    __shared__ __align__(16) unsigned Bs[16][136];   // [k][n] pad 136 -> conflict-free
    int tid = threadIdx.x;
    int lane = tid & 31, warp = tid >> 5;
    int wm = warp >> 1, wn = warp & 1;           // 4 x 2 warp grid; warp tile 32 x 64
    int gq = lane >> 2, ctg = lane & 3;
    int rowBase = blockIdx.y * 128, colBase = blockIdx.x * 128;

    float c[2][8][4];
#pragma unroll
    for (int t = 0; t < 2; ++t)
#pragma unroll
        for (int j = 0; j < 8; ++j)
#pragma unroll
            for (int e = 0; e < 4; ++e) c[t][j][e] = 0.f;

    int am = tid & 127;   // A row loaded by this thread
    int aq = tid >> 7;    // which k-half (0: k 0..7, 1: k 8..15)
    int bn4 = tid & 31;   // B float4 column
    int bk = tid >> 5;    // B k-row (and +8)

    for (int part = 0; part < 2; ++part) {
        const float* A = part ? A1 : A0;
        const float* B = part ? B1 : B0;
        int K = part ? K1 : K0;
        if (A == nullptr) continue;
        const float* Arow = A + (size_t)(rowBase + am) * K;
        for (int k0 = 0; k0 < K; k0 += 16) {
#pragma unroll
            for (int i = 0; i < 2; ++i) {
                float4 v = *(const float4*)(Arow + k0 + aq * 8 + i * 4);
                uint4 u = make_uint4(f2tf32(v.x), f2tf32(v.y), f2tf32(v.z), f2tf32(v.w));
                *(uint4*)&As[am][aq * 8 + i * 4] = u;
            }
#pragma unroll
            for (int i = 0; i < 2; ++i) {
                int kr = bk + i * 8;
                float4 v = *(const float4*)(B + (size_t)(k0 + kr) * N + colBase + bn4 * 4);
                uint4 u = make_uint4(f2tf32(v.x), f2tf32(v.y), f2tf32(v.z), f2tf32(v.w));
                *(uint4*)&Bs[kr][bn4 * 4] = u;
            }
            __syncthreads();
#pragma unroll
            for (int ks = 0; ks < 16; ks += 8) {
                unsigned a[2][4], b[8][2];
#pragma unroll
                for (int t = 0; t < 2; ++t) {
                    int row = wm * 32 + t * 16 + gq;
                    a[t][0] = As[row][ks + ctg];
                    a[t][1] = As[row + 8][ks + ctg];
                    a[t][2] = As[row][ks + ctg + 4];
                    a[t][3] = As[row + 8][ks + ctg + 4];
                }
#pragma unroll
                for (int j = 0; j < 8; ++j) {
                    int col = wn * 64 + j * 8 + gq;
                    b[j][0] = Bs[ks + ctg][col];
                    b[j][1] = Bs[ks + ctg + 4][col];
                }
#pragma unroll
                for (int t = 0; t < 2; ++t)
#pragma unroll
                    for (int j = 0; j < 8; ++j)
                        mma_tf32(c[t][j][0], c[t][j][1], c[t][j][2], c[t][j][3],
                                 a[t][0], a[t][1], a[t][2], a[t][3],
                                 b[j][0], b[j][1]);
            }
            __syncthreads();
        }
    }

#pragma unroll
    for (int t = 0; t < 2; ++t) {
#pragma unroll
        for (int half = 0; half < 2; ++half) {
            int r = rowBase + wm * 32 + t * 16 + gq + half * 8;
#pragma unroll
            for (int j = 0; j < 8; ++j) {
                int col = colBase + wn * 64 + j * 8 + ctg * 2;
                float v0 = c[t][j][half * 2 + 0];
                float v1 = c[t][j][half * 2 + 1];
                if (bias) { v0 += bias[col] * biasScale; v1 += bias[col + 1] * biasScale; }
                if (R) {
                    v0 += R[(size_t)r * N + col];
                    v1 += R[(size_t)r * N + col + 1];
                }
                if (act == 1) { v0 = siluf(v0); v1 = siluf(v1); }
                else if (act == 2) { v0 = tanhf(v0); v1 = tanhf(v1); }
                *(float2*)&Cout[(size_t)r * N + col] = make_float2(v0, v1);
            }
        }
    }
}

// ---------------- per-edge hidden + silu + aggregate ----------------
__global__ __launch_bounds__(256) void edge_kernel(const float* __restrict__ ta,
                                                   const float* __restrict__ tb,
                                                   const int* __restrict__ knn,
                                                   const float* __restrict__ ea,
                                                   const float* __restrict__ W1c,
                                                   float* __restrict__ s) {
    __shared__ int   ksh[Kk];
    __shared__ float esh[Kk * 4];
    int n = blockIdx.x;
    int c = threadIdx.x;
    if (c < Kk) ksh[c] = knn[n * Kk + c];
    if (c < Kk * 4) esh[c] = ea[n * Kk * 4 + c];
    __syncthreads();
    float w0 = W1c[c], w1 = W1c[DH + c], w2 = W1c[2 * DH + c], w3 = W1c[3 * DH + c];
    float tav = ta[n * DH + c];
    float acc = 0.f;
#pragma unroll
    for (int j = 0; j < Kk; ++j) {
        int src = ksh[j];
        float v = tav + tb[src * DH + c]
                + esh[4 * j] * w0 + esh[4 * j + 1] * w1
                + esh[4 * j + 2] * w2 + esh[4 * j + 3] * w3;
        acc += siluf(v);
    }
    s[n * DH + c] = acc;
}

// ---------------- graph norm (deterministic two-stage) ----------------
__global__ void norm_sum(const float* __restrict__ h, float* __restrict__ part) {
    int b = blockIdx.x >> 3, sl = blockIdx.x & 7, c = threadIdx.x;
    int row0 = (b << 10) + (sl << 7);
    float acc = 0.f;
    for (int r = 0; r < 128; ++r) acc += h[(row0 + r) * DM + c];
    part[blockIdx.x * DM + c] = acc;
}
__global__ void norm_fin(const float* __restrict__ part, float* __restrict__ out) {
    int b = blockIdx.x, c = threadIdx.x;
    float acc = 0.f;
    for (int s = 0; s < 8; ++s) acc += part[(b * 8 + s) * DM + c];
    out[b * DM + c] = acc * (1.f / 1024.f);
}
__global__ void norm_apply(float* __restrict__ h, const float* __restrict__ mean,
                           const float* __restrict__ ms, float* __restrict__ part) {
    int b = blockIdx.x >> 3, sl = blockIdx.x & 7, c = threadIdx.x;
    int row0 = (b << 10) + (sl << 7);
    float mv = mean[b * DM + c] * ms[c];
    float acc = 0.f;
    for (int r = 0; r < 128; ++r) {
        float o = h[(row0 + r) * DM + c] - mv;
        h[(row0 + r) * DM + c] = o;
        acc += o * o;
    }
    part[blockIdx.x * DM + c] = acc;
}
__global__ void norm_scale(float* __restrict__ h, const float* __restrict__ var,
                           const float* __restrict__ w, const float* __restrict__ bb) {
    int b = blockIdx.x >> 3, sl = blockIdx.x & 7, c = threadIdx.x;
    int row0 = (b << 10) + (sl << 7);
    float inv = 1.f / sqrtf(var[b * DM + c] + 1e-5f);
    float wc = w[c] * inv, bc = bb[c];
    for (int r = 0; r < 128; ++r)
        h[(row0 + r) * DM + c] = h[(row0 + r) * DM + c] * wc + bc;
}

// ---------------- gate logit GEMV ----------------
__global__ void gl_kernel(const float* __restrict__ ghid, const float* __restrict__ W2,
                          const float* __restrict__ b2, float* __restrict__ gl) {
    int node = blockIdx.x * 8 + (threadIdx.x >> 5);
    int lane = threadIdx.x & 31;
    float acc = 0.f;
#pragma unroll
    for (int r = 0; r < 4; ++r) acc += ghid[node * DM + lane + 32 * r] * W2[lane + 32 * r];
#pragma unroll
    for (int o = 16; o; o >>= 1) acc += __shfl_down_sync(0xffffffffu, acc, o);
    if (lane == 0) gl[node] = acc + b2[0];
}

// ---------------- softmax pool + head ----------------
__global__ __launch_bounds__(1024) void pool_head(const float* __restrict__ h,
                                                  const float* __restrict__ gl,
                                                  const float* __restrict__ hW1,
                                                  const float* __restrict__ hb1,
                                                  const float* __restrict__ hW2,
                                                  const float* __restrict__ hb2,
                                                  float* __restrict__ out) {
    __shared__ float red[1024];
    __shared__ float ash[1024];
    __shared__ float pool[1024];
    __shared__ float pvec[128];
    __shared__ float hid[128];
    int g = blockIdx.x, tid = threadIdx.x;
    float gv = gl[g * NPG + tid];
    red[tid] = gv;
    __syncthreads();
    for (int s = 512; s > 0; s >>= 1) {
        if (tid < s) red[tid] = fmaxf(red[tid], red[tid + s]);
        __syncthreads();
    }
    float gmax = red[0];
    __syncthreads();
    float e = expf(gv - gmax);
    red[tid] = e;
    __syncthreads();
    for (int s = 512; s > 0; s >>= 1) {
        if (tid < s) red[tid] += red[tid + s];
        __syncthreads();
    }
    float ssum = red[0];
    __syncthreads();
    ash[tid] = e / ssum;
    __syncthreads();
    int r = tid >> 7, c = tid & 127;
    float acc = 0.f;
    for (int n = r; n < NPG; n += 8)
        acc += ash[n] * h[(g * NPG + n) * DM + c];
    pool[tid] = acc;
    __syncthreads();
    if (tid < 128) {
        float p = 0.f;
        for (int q = 0; q < 8; ++q) p += pool[q * 128 + tid];
        pvec[tid] = p;
    }
    __syncthreads();
    if (tid < 128) {
        float t = hb1[tid];
        for (int k = 0; k < 128; ++k) t += pvec[k] * hW1[k * DM + tid];
        hid[tid] = siluf(t);
    }
    __syncthreads();
    if (tid < 128) red[tid] = hid[tid] * hW2[tid];
    __syncthreads();
    for (int s = 64; s > 0; s >>= 1) {
        if (tid < s) red[tid] += red[tid + s];
        __syncthreads();
    }
    if (tid == 0) out[g] = red[0] + hb2[0];
}

// ---------------- host orchestration ----------------
extern "C" void kernel_launch(void* const* d_in, const int* in_sizes, int n_in,
                              void* d_out, int out_size) {
    (void)in_sizes; (void)n_in; (void)out_size;
    const float* x      = (const float*)d_in[0];
    const float* in_W1  = (const float*)d_in[2];
    const float* in_b1  = (const float*)d_in[3];
    const float* in_W2  = (const float*)d_in[4];
    const float* in_b2  = (const float*)d_in[5];
    const float* msg_W1 = (const float*)d_in[6];
    const float* msg_b1 = (const float*)d_in[7];
    const float* msg_W2 = (const float*)d_in[8];
    const float* msg_b2 = (const float*)d_in[9];
    const float* upd_W1 = (const float*)d_in[10];
    const float* upd_b1 = (const float*)d_in[11];
    const float* upd_W2 = (const float*)d_in[12];
    const float* upd_b2 = (const float*)d_in[13];
    const float* norm_w = (const float*)d_in[14];
    const float* norm_b = (const float*)d_in[15];
    const float* norm_ms= (const float*)d_in[16];
    const float* gate_W1= (const float*)d_in[17];
    const float* gate_b1= (const float*)d_in[18];
    const float* gate_W2= (const float*)d_in[19];
    const float* gate_b2= (const float*)d_in[20];
    const float* head_W1= (const float*)d_in[21];
    const float* head_b1= (const float*)d_in[22];
    const float* head_W2= (const float*)d_in[23];
    const float* head_b2= (const float*)d_in[24];
    float* out = (float*)d_out;

    float *hb, *tab, *tbb, *sb, *aggb, *uhb, *eab, *glb, *partb, *meanb, *varb;
    int* knnb;
    cudaGetSymbolAddress((void**)&hb,   g_h);
    cudaGetSymbolAddress((void**)&tab,  g_ta);
    cudaGetSymbolAddress((void**)&tbb,  g_tb);
    cudaGetSymbolAddress((void**)&sb,   g_s);
    cudaGetSymbolAddress((void**)&aggb, g_agg);
    cudaGetSymbolAddress((void**)&uhb,  g_uh);
    cudaGetSymbolAddress((void**)&eab,  g_ea);
    cudaGetSymbolAddress((void**)&knnb, g_knn);
    cudaGetSymbolAddress((void**)&glb,  g_gl);
    cudaGetSymbolAddress((void**)&partb,g_part);
    cudaGetSymbolAddress((void**)&meanb,g_mean);
    cudaGetSymbolAddress((void**)&varb, g_var);

    // 1. KNN + edge attrs
    knn_kernel<<<Nn, 256>>>(x, knnb, eab);

    // 2. input MLP: hidden -> g_ta (N x 128), then h = hidden @ in_W2 + b2
    in_hidden_kernel<<<Nn, DM>>>(x, in_W1, in_b1, tab);
    {
        dim3 grid(DM / 128, Nn / 128);
        gemm_tf32<<<grid, 256>>>(tab, in_W2, DM, nullptr, nullptr, 0,
                                 in_b2, 1.f, nullptr, hb, DM, 0);
    }

    for (int i = 0; i < Ll; ++i) {
        const float* W1i = msg_W1 + (size_t)i * 260 * DH;
        const float* b1i = msg_b1 + (size_t)i * DH;
        const float* W2i = msg_W2 + (size_t)i * DH * DM;
        const float* b2i = msg_b2 + (size_t)i * DM;
        const float* U1i = upd_W1 + (size_t)i * 2 * DM * DH;
        const float* ub1i= upd_b1 + (size_t)i * DH;
        const float* U2i = upd_W2 + (size_t)i * DH * DM;
        const float* ub2i= upd_b2 + (size_t)i * DM;
        const float* nwi = norm_w + (size_t)i * DM;
        const float* nbi = norm_b + (size_t)i * DM;
        const float* nmi = norm_ms+ (size_t)i * DM;

        dim3 grid256(DH / 128, Nn / 128);
        dim3 grid128(DM / 128, Nn / 128);
        // ta = h @ W1[0:128] + b1 ; tb = h @ W1[128:256]
        gemm_tf32<<<grid256, 256>>>(hb, W1i, DM, nullptr, nullptr, 0,
                                    b1i, 1.f, nullptr, tab, DH, 0);
        gemm_tf32<<<grid256, 256>>>(hb, W1i + DM * DH, DM, nullptr, nullptr, 0,
                                    nullptr, 0.f, nullptr, tbb, DH, 0);
        // s[n] = sum_j silu(ta[n] + tb[src] + ea @ W1[256:260])
        edge_kernel<<<Nn, DH>>>(tab, tbb, knnb, eab, W1i + 2 * DM * DH, sb);
        // agg = s @ W2 + 12*b2
        gemm_tf32<<<grid128, 256>>>(sb, W2i, DH, nullptr, nullptr, 0,
                                    b2i, 12.f, nullptr, aggb, DM, 0);
        // uh = silu(h @ U1[0:128] + agg @ U1[128:256] + ub1)
        gemm_tf32<<<grid256, 256>>>(hb, U1i, DM, aggb, U1i + DM * DH, DM,
                                    ub1i, 1.f, nullptr, uhb, DH, 1);
        // h = h + uh @ U2 + ub2
        gemm_tf32<<<grid128, 256>>>(uhb, U2i, DH, nullptr, nullptr, 0,
                                    ub2i, 1.f, hb, hb, DM, 0);
        // graph norm
        norm_sum<<<Bg * 8, DM>>>(hb, partb);
        norm_fin<<<Bg, DM>>>(partb, meanb);
        norm_apply<<<Bg * 8, DM>>>(hb, meanb, nmi, partb);
        norm_fin<<<Bg, DM>>>(partb, varb);
        norm_scale<<<Bg * 8, DM>>>(hb, varb, nwi, nbi);
    }

    // gate: ghid = tanh(h @ gate_W1 + gate_b1)  (reuse g_ta)
    {
        dim3 grid(DM / 128, Nn / 128);
        gemm_tf32<<<grid, 256>>>(hb, gate_W1, DM, nullptr, nullptr, 0,
                                 gate_b1, 1.f, nullptr, tab, DM, 2);
    }
    gl_kernel<<<Nn / 8, 256>>>(tab, gate_W2, gate_b2, glb);
    pool_head<<<Bg, 1024>>>(hb, glb, head_W1, head_b1, head_W2, head_b2, out);
}